// round 11
// baseline (speedup 1.0000x reference)
#include <cuda_runtime.h>
#include <cuda_fp16.h>
#include <cstdint>
#include <cstddef>

#define BB 4
#define SS 2048
#define DD 1024
#define HH 16
#define DHH 64

// ---------------------------------------------------------------------------
// Scratch: everything single fp16.
// X: [BS, D]. W: [3][D, D]. Q (pre-scaled 0.125*log2e) / K: [BH,S,DH].
// Vt: [BH,DH,S].
// ---------------------------------------------------------------------------
__device__ uint16_t g_Xh[BB * SS * DD];
__device__ uint16_t g_Wh[3 * DD * DD];
__device__ uint16_t g_Qh[BB * HH * SS * DHH];
__device__ uint16_t g_Kh[BB * HH * SS * DHH];
__device__ uint16_t g_Vth[BB * HH * SS * DHH];

// ---------------------------------------------------------------------------
// Helpers
// ---------------------------------------------------------------------------
__device__ __forceinline__ uint32_t smem_u32(const void* p) {
    uint32_t a;
    asm("{ .reg .u64 t; cvta.to.shared.u64 t, %1; cvt.u32.u64 %0, t; }"
        : "=r"(a) : "l"(p));
    return a;
}
__device__ __forceinline__ void cp_async16(uint32_t dst, const void* src) {
    asm volatile("cp.async.cg.shared.global [%0], [%1], 16;"
                 :: "r"(dst), "l"(src) : "memory");
}
#define CP_COMMIT() asm volatile("cp.async.commit_group;" ::: "memory")
#define CP_WAIT(n)  asm volatile("cp.async.wait_group %0;" :: "n"(n) : "memory")

__device__ __forceinline__ void ldsm4(uint32_t* r, uint32_t addr) {
    asm volatile("ldmatrix.sync.aligned.m8n8.x4.shared.b16 {%0,%1,%2,%3}, [%4];"
                 : "=r"(r[0]), "=r"(r[1]), "=r"(r[2]), "=r"(r[3]) : "r"(addr));
}

__device__ __forceinline__ uint32_t packh(float x, float y) {
    uint32_t r;
    asm("cvt.rn.f16x2.f32 %0, %1, %2;" : "=r"(r) : "f"(y), "f"(x));
    return r;
}
__device__ __forceinline__ float ex2(float x) {
    float r;
    asm("ex2.approx.ftz.f32 %0, %1;" : "=f"(r) : "f"(x));
    return r;
}

__device__ __forceinline__ void mma_f16(float* d, const uint32_t* a, const uint32_t* b) {
    asm volatile(
        "mma.sync.aligned.m16n8k16.row.col.f32.f16.f16.f32 "
        "{%0,%1,%2,%3}, {%4,%5,%6,%7}, {%8,%9}, {%0,%1,%2,%3};"
        : "+f"(d[0]), "+f"(d[1]), "+f"(d[2]), "+f"(d[3])
        : "r"(a[0]), "r"(a[1]), "r"(a[2]), "r"(a[3]), "r"(b[0]), "r"(b[1]));
}

// Swizzled word offsets.
#define WOFF16(r, w) (((r) >> 1) * 32 + (((((r) & 1) << 4) | (w)) ^ ((((r) >> 1) & 7) << 2)))
#define WOFF32(r, w) ((r) * 32 + ((w) ^ (((r) & 7) << 2)))

// ---------------------------------------------------------------------------
// Convert kernels: fp32 -> fp16.
// ---------------------------------------------------------------------------
__global__ void __launch_bounds__(256) cvth_kernel(
    const float* __restrict__ s, uint16_t* __restrict__ h, int n4)
{
    int i = blockIdx.x * 256 + threadIdx.x;
    if (i >= n4) return;
    float4 v = reinterpret_cast<const float4*>(s)[i];
    reinterpret_cast<uint2*>(h)[i] = make_uint2(packh(v.x, v.y), packh(v.z, v.w));
}
__global__ void __launch_bounds__(256) cvth3_kernel(
    const float* __restrict__ s0, const float* __restrict__ s1,
    const float* __restrict__ s2, uint16_t* __restrict__ h, int n4)
{
    int i = blockIdx.x * 256 + threadIdx.x;
    if (i >= n4) return;
    const float* s = (blockIdx.z == 0) ? s0 : (blockIdx.z == 1) ? s1 : s2;
    float4 v = reinterpret_cast<const float4*>(s)[i];
    reinterpret_cast<uint2*>(h + (size_t)blockIdx.z * DD * DD)[i] =
        make_uint2(packh(v.x, v.y), packh(v.z, v.w));
}

// ---------------------------------------------------------------------------
// Projection (merged Q/K/V): 1-pass fp16 HMMA. Y = Xh @ Wh^T + bias.
// 64(M)x128(N) tile, BK=32, 4 warps (1M x 4N), 128 threads, 3-stage pipe.
// ---------------------------------------------------------------------------
#define NSTAGE 3
#define NKT (DD / 32)
#define PROJ_STAGE_W 3072            // X 1024 + W 2048 words = 12 KB

__global__ void __launch_bounds__(128, 1) proj_mma(
    const float* __restrict__ bq, const float* __restrict__ bk,
    const float* __restrict__ bv)
{
    extern __shared__ uint32_t smw[];
    const uint32_t smb = smem_u32(smw);

    const int which = blockIdx.z;
    const float* bias = (which == 0) ? bq : (which == 1) ? bk : bv;

    const __half* Xh = (const __half*)g_Xh;
    const __half* Wh = (const __half*)(g_Wh + (size_t)which * DD * DD);

    const int tid = threadIdx.x;
    const int wid = tid >> 5, lane = tid & 31;
    const int g = lane >> 2, tig = lane & 3;
    const int wn = wid;
    const int m0 = blockIdx.y * 64, n0 = blockIdx.x * 128;

    const int lsub = lane >> 3, lr8 = lane & 7;
    const int a_radd = (lsub & 1) * 8 + lr8;
    const int a_cadd = lsub >> 1;
    const int b_radd = (lsub >> 1) * 8 + lr8;
    const int b_cadd = lsub & 1;

    auto load_stage = [&](int kt) {
        const int st = kt % NSTAGE;
        const int k0 = kt * 32;
        const uint32_t base = smb + (uint32_t)st * PROJ_STAGE_W * 4u;
        #pragma unroll
        for (int i = 0; i < 6; ++i) {
            const int idx = tid + 128 * i;          // 0..767
            uint32_t dst;
            const __half* src;
            if (idx < 256) {                        // X tile: 64 rows x 4 chunks
                const int row = idx >> 2, c = idx & 3;
                dst = base + 4u * (uint32_t)WOFF16(row, c * 4);
                src = Xh + (size_t)(m0 + row) * DD + k0 + c * 8;
            } else {                                // W tile: 128 rows x 4 chunks
                const int j = idx - 256;
                const int row = j >> 2, c = j & 3;
                dst = base + 4096u + 4u * (uint32_t)WOFF16(row, c * 4);
                src = Wh + (size_t)(n0 + row) * DD + k0 + c * 8;
            }
            cp_async16(dst, src);
        }
        CP_COMMIT();
    };

    float acc[4][4][4];
    #pragma unroll
    for (int i = 0; i < 4; ++i)
        #pragma unroll
        for (int j = 0; j < 4; ++j)
            #pragma unroll
            for (int r = 0; r < 4; ++r) acc[i][j][r] = 0.f;

    load_stage(0);
    load_stage(1);

    for (int kt = 0; kt < NKT; ++kt) {
        CP_WAIT(1);
        __syncthreads();
        if (kt + 2 < NKT) load_stage(kt + 2);
        else CP_COMMIT();

        const uint32_t base = smb + (uint32_t)(kt % NSTAGE) * PROJ_STAGE_W * 4u;
        const uint32_t Ah = base, Bh = base + 4096u;

        #pragma unroll
        for (int ks = 0; ks < 2; ++ks) {
            uint32_t bh[2][4];
            #pragma unroll
            for (int p = 0; p < 2; ++p) {
                const int rn = wn * 32 + p * 16 + b_radd;
                const uint32_t off = 4u * (uint32_t)WOFF16(rn, 4 * (2 * ks + b_cadd));
                ldsm4(bh[p], Bh + off);
            }
            #pragma unroll
            for (int mf = 0; mf < 4; ++mf) {
                const int rA = mf * 16 + a_radd;
                const uint32_t off = 4u * (uint32_t)WOFF16(rA, 4 * (2 * ks + a_cadd));
                uint32_t ah[4];
                ldsm4(ah, Ah + off);
                #pragma unroll
                for (int nf = 0; nf < 4; ++nf)
                    mma_f16(acc[mf][nf], ah, &bh[nf >> 1][(nf & 1) * 2]);
            }
        }
    }

    // ---- epilogue ----
    // Q pre-scaled by 0.125*log2(e) so QK^T emits log2-domain scores.
    const float qscale = (which == 0) ? 0.18033688011116027f : 1.0f;

    #pragma unroll
    for (int mf = 0; mf < 4; ++mf) {
        #pragma unroll
        for (int nf = 0; nf < 4; ++nf) {
            const int col = n0 + wn * 32 + nf * 8 + 2 * tig;
            const int h = col >> 6, dh = col & 63;
            const float2 bb = *reinterpret_cast<const float2*>(bias + col);
            #pragma unroll
            for (int half = 0; half < 2; ++half) {
                const int r = m0 + mf * 16 + g + 8 * half;
                const int b_ = r >> 11;
                const int sq = r & (SS - 1);
                const int bh_ = b_ * HH + h;
                const float y0 = (acc[mf][nf][2 * half + 0] + bb.x) * qscale;
                const float y1 = (acc[mf][nf][2 * half + 1] + bb.y) * qscale;
                const uint32_t h2 = packh(y0, y1);
                if (which == 0) {
                    *reinterpret_cast<uint32_t*>(
                        g_Qh + ((size_t)bh_ * SS + sq) * DHH + dh) = h2;
                } else if (which == 1) {
                    *reinterpret_cast<uint32_t*>(
                        g_Kh + ((size_t)bh_ * SS + sq) * DHH + dh) = h2;
                } else {
                    const size_t i0 = ((size_t)bh_ * DHH + dh) * SS + sq;
                    const size_t i1 = ((size_t)bh_ * DHH + dh + 1) * SS + sq;
                    g_Vth[i0] = (uint16_t)(h2 & 0xffff);
                    g_Vth[i1] = (uint16_t)(h2 >> 16);
                }
            }
        }
    }
}

// ---------------------------------------------------------------------------
// Flash attention, static-max, phase-interleaved: each 16-key group's exp/pack
// runs as soon as its S fragment completes, overlapping MUFU with the HMMA
// stream of later groups. 64 q-rows per CTA (4 warps), 64-key blocks,
// double-buffered. Reg-capped for 4 CTAs/SM.
// ---------------------------------------------------------------------------
#define ATTN_STAGE_W 4096            // 2 tiles (K, Vt) x 2048 words = 16 KB

__global__ void __launch_bounds__(128, 4) attn_mma(float* __restrict__ out)
{
    extern __shared__ uint32_t smw[];
    const uint32_t smb = smem_u32(smw);

    const int tid = threadIdx.x;
    const int wid = tid >> 5, lane = tid & 31;
    const int g = lane >> 2, tig = lane & 3;
    const int bx = (int)gridDim.x - 1 - (int)blockIdx.x;  // heavy tiles first
    const int bh = blockIdx.y;
    const int q0 = bx * 64;

    const int lsub = lane >> 3, lr8 = lane & 7;
    const int b_radd = (lsub >> 1) * 8 + lr8;
    const int b_cadd = lsub & 1;

    const __half* Qg  = (const __half*)g_Qh  + (size_t)bh * SS * DHH;
    const __half* Kg  = (const __half*)g_Kh  + (size_t)bh * SS * DHH;
    const __half* Vtg = (const __half*)g_Vth + (size_t)bh * DHH * SS;

    const int qrA = q0 + wid * 16 + g;

    // Q fragments (single fp16, pre-scaled 0.125*log2e)
    uint32_t qh[4][4];
    #pragma unroll
    for (int ks = 0; ks < 4; ++ks) {
        const int w0 = 8 * ks + tig, w1 = w0 + 4;
        const uint32_t* ra = reinterpret_cast<const uint32_t*>(Qg + (size_t)qrA * DHH);
        const uint32_t* rb = reinterpret_cast<const uint32_t*>(Qg + (size_t)(qrA + 8) * DHH);
        qh[ks][0] = ra[w0]; qh[ks][1] = rb[w0]; qh[ks][2] = ra[w1]; qh[ks][3] = rb[w1];
    }

    auto load_stage = [&](int kb) {
        const int k0 = kb * 64;
        const uint32_t base = smb + (uint32_t)(kb & 1) * ATTN_STAGE_W * 4u;
        #pragma unroll
        for (int i = 0; i < 8; ++i) {
            const int idx = tid + 128 * i;          // 0..1023
            const int tile = idx >> 9;
            const int rem = idx & 511;
            const int row = rem >> 3, c = rem & 7;
            const uint32_t dst = base + (uint32_t)tile * 8192u + 4u * (uint32_t)WOFF32(row, c * 4);
            const __half* src = (tile == 0)
                ? Kg  + (size_t)(k0 + row) * DHH + c * 8
                : Vtg + (size_t)row * SS + k0 + c * 8;
            cp_async16(dst, src);
        }
        CP_COMMIT();
    };

    float O[8][4];
    #pragma unroll
    for (int d = 0; d < 8; ++d)
        #pragma unroll
        for (int r = 0; r < 4; ++r) O[d][r] = 0.f;
    float rsA = 0.f, rsB = 0.f;      // per-thread partial row sums

    const int nkb = bx + 1;
    load_stage(0);

    for (int kb = 0; kb < nkb; ++kb) {
        CP_WAIT(0);
        __syncthreads();
        if (kb + 1 < nkb) load_stage(kb + 1);

        const uint32_t base = smb + (uint32_t)(kb & 1) * ATTN_STAGE_W * 4u;
        const uint32_t KS = base, VS = base + 8192u;

        // ---- per 16-key group: QK mma chain, then immediately exp/pack ----
        uint32_t ph[4][4];
        #pragma unroll
        for (int p = 0; p < 4; ++p) {
            float S0[4] = {0.f, 0.f, 0.f, 0.f};
            float S1[4] = {0.f, 0.f, 0.f, 0.f};
            const int rn = p * 16 + b_radd;
            #pragma unroll
            for (int ks = 0; ks < 4; ++ks) {
                const uint32_t off = 4u * (uint32_t)WOFF32(rn, 4 * (2 * ks + b_cadd));
                uint32_t k4[4];
                ldsm4(k4, KS + off);
                mma_f16(S0, qh[ks], k4);
                mma_f16(S1, qh[ks], k4 + 2);
            }

            if (kb == bx) {                      // diagonal-block causal mask
                const int key0 = kb * 64 + p * 16 + 2 * tig;      // nf = 2p
                const int key1 = key0 + 8;                         // nf = 2p+1
                if (key0     > qrA)     S0[0] = -1e30f;
                if (key0 + 1 > qrA)     S0[1] = -1e30f;
                if (key0     > qrA + 8) S0[2] = -1e30f;
                if (key0 + 1 > qrA + 8) S0[3] = -1e30f;
                if (key1     > qrA)     S1[0] = -1e30f;
                if (key1 + 1 > qrA)     S1[1] = -1e30f;
                if (key1     > qrA + 8) S1[2] = -1e30f;
                if (key1 + 1 > qrA + 8) S1[3] = -1e30f;
            }

            S0[0] = ex2(S0[0]); rsA += S0[0];
            S0[1] = ex2(S0[1]); rsA += S0[1];
            S0[2] = ex2(S0[2]); rsB += S0[2];
            S0[3] = ex2(S0[3]); rsB += S0[3];
            S1[0] = ex2(S1[0]); rsA += S1[0];
            S1[1] = ex2(S1[1]); rsA += S1[1];
            S1[2] = ex2(S1[2]); rsB += S1[2];
            S1[3] = ex2(S1[3]); rsB += S1[3];

            ph[p][0] = packh(S0[0], S0[1]);
            ph[p][1] = packh(S0[2], S0[3]);
            ph[p][2] = packh(S1[0], S1[1]);
            ph[p][3] = packh(S1[2], S1[3]);
        }

        // ---- O += P V (1-pass fp16, no rescale) ----
        #pragma unroll
        for (int ks = 0; ks < 4; ++ks) {
            #pragma unroll
            for (int p = 0; p < 4; ++p) {
                const int rv = p * 16 + b_radd;
                const uint32_t off = 4u * (uint32_t)WOFF32(rv, 4 * (2 * ks + b_cadd));
                uint32_t v4[4];
                ldsm4(v4, VS + off);
                mma_f16(O[2 * p],     ph[ks], v4);
                mma_f16(O[2 * p + 1], ph[ks], v4 + 2);
            }
        }
    }

    // ---- final row-sum reduce (once) + normalize + store ----
    float lA = rsA, lB = rsB;
    lA += __shfl_xor_sync(0xffffffffu, lA, 1);
    lA += __shfl_xor_sync(0xffffffffu, lA, 2);
    lB += __shfl_xor_sync(0xffffffffu, lB, 1);
    lB += __shfl_xor_sync(0xffffffffu, lB, 2);

    const int b_ = bh >> 4, h = bh & 15;
    const float iA = 1.f / lA, iB = 1.f / lB;
    #pragma unroll
    for (int df = 0; df < 8; ++df) {
        const int col = h * DHH + df * 8 + 2 * tig;
        float2 va = { O[df][0] * iA, O[df][1] * iA };
        float2 vb = { O[df][2] * iB, O[df][3] * iB };
        *reinterpret_cast<float2*>(out + ((size_t)(b_ * SS + qrA)) * DD + col) = va;
        *reinterpret_cast<float2*>(out + ((size_t)(b_ * SS + qrA + 8)) * DD + col) = vb;
    }
}

// ---------------------------------------------------------------------------
// Launch
// ---------------------------------------------------------------------------
extern "C" void kernel_launch(void* const* d_in, const int* in_sizes, int n_in,
                              void* d_out, int out_size)
{
    const float* x  = (const float*)d_in[0];
    const float* Wq = (const float*)d_in[2];
    const float* bq = (const float*)d_in[3];
    const float* Wk = (const float*)d_in[4];
    const float* bk = (const float*)d_in[5];
    const float* Wv = (const float*)d_in[6];
    const float* bv = (const float*)d_in[7];
    float* out = (float*)d_out;

    void *pXh, *pWh;
    cudaGetSymbolAddress(&pXh, g_Xh);
    cudaGetSymbolAddress(&pWh, g_Wh);

    const int nX4 = BB * SS * DD / 4;
    const int nW4 = DD * DD / 4;
    cvth_kernel<<<(nX4 + 255) / 256, 256>>>(x, (uint16_t*)pXh, nX4);
    cvth3_kernel<<<dim3((nW4 + 255) / 256, 1, 3), 256>>>(Wq, Wk, Wv, (uint16_t*)pWh, nW4);

    const int PROJ_SMEM = NSTAGE * PROJ_STAGE_W * 4;   // 36 KB
    cudaFuncSetAttribute(proj_mma, cudaFuncAttributeMaxDynamicSharedMemorySize, PROJ_SMEM);
    const int ATTN_SMEM = 2 * ATTN_STAGE_W * 4;        // 32 KB
    cudaFuncSetAttribute(attn_mma, cudaFuncAttributeMaxDynamicSharedMemorySize, ATTN_SMEM);

    dim3 gp(DD / 128, (BB * SS) / 64, 3);              // (8, 128, 3)
    proj_mma<<<gp, 128, PROJ_SMEM>>>(bq, bk, bv);

    attn_mma<<<dim3(SS / 64, BB * HH), 128, ATTN_SMEM>>>(out);
}

// round 13
// speedup vs baseline: 1.0043x; 1.0043x over previous
#include <cuda_runtime.h>
#include <cuda_fp16.h>
#include <cstdint>
#include <cstddef>

#define BB 4
#define SS 2048
#define DD 1024
#define HH 16
#define DHH 64

// ---------------------------------------------------------------------------
// Scratch: everything single fp16.
// X: [BS, D]. W: [3][D, D]. Q (pre-scaled 0.125*log2e) / K: [BH,S,DH].
// Vt: [BH,DH,S].
// ---------------------------------------------------------------------------
__device__ uint16_t g_Xh[BB * SS * DD];
__device__ uint16_t g_Wh[3 * DD * DD];
__device__ uint16_t g_Qh[BB * HH * SS * DHH];
__device__ uint16_t g_Kh[BB * HH * SS * DHH];
__device__ uint16_t g_Vth[BB * HH * SS * DHH];

// ---------------------------------------------------------------------------
// Helpers
// ---------------------------------------------------------------------------
__device__ __forceinline__ uint32_t smem_u32(const void* p) {
    uint32_t a;
    asm("{ .reg .u64 t; cvta.to.shared.u64 t, %1; cvt.u32.u64 %0, t; }"
        : "=r"(a) : "l"(p));
    return a;
}
__device__ __forceinline__ void cp_async16(uint32_t dst, const void* src) {
    asm volatile("cp.async.cg.shared.global [%0], [%1], 16;"
                 :: "r"(dst), "l"(src) : "memory");
}
#define CP_COMMIT() asm volatile("cp.async.commit_group;" ::: "memory")
#define CP_WAIT(n)  asm volatile("cp.async.wait_group %0;" :: "n"(n) : "memory")

__device__ __forceinline__ void ldsm4(uint32_t* r, uint32_t addr) {
    asm volatile("ldmatrix.sync.aligned.m8n8.x4.shared.b16 {%0,%1,%2,%3}, [%4];"
                 : "=r"(r[0]), "=r"(r[1]), "=r"(r[2]), "=r"(r[3]) : "r"(addr));
}

__device__ __forceinline__ uint32_t packh(float x, float y) {
    uint32_t r;
    asm("cvt.rn.f16x2.f32 %0, %1, %2;" : "=r"(r) : "f"(y), "f"(x));
    return r;
}
// packed exp2 on two fp16 lanes (one MUFU-class op for both)
__device__ __forceinline__ uint32_t h2ex2(uint32_t x) {
    uint32_t r;
    asm("ex2.approx.f16x2 %0, %1;" : "=r"(r) : "r"(x));
    return r;
}

__device__ __forceinline__ void mma_f16(float* d, const uint32_t* a, const uint32_t* b) {
    asm volatile(
        "mma.sync.aligned.m16n8k16.row.col.f32.f16.f16.f32 "
        "{%0,%1,%2,%3}, {%4,%5,%6,%7}, {%8,%9}, {%0,%1,%2,%3};"
        : "+f"(d[0]), "+f"(d[1]), "+f"(d[2]), "+f"(d[3])
        : "r"(a[0]), "r"(a[1]), "r"(a[2]), "r"(a[3]), "r"(b[0]), "r"(b[1]));
}

// Swizzled word offsets.
#define WOFF16(r, w) (((r) >> 1) * 32 + (((((r) & 1) << 4) | (w)) ^ ((((r) >> 1) & 7) << 2)))
#define WOFF32(r, w) ((r) * 32 + ((w) ^ (((r) & 7) << 2)))

// ---------------------------------------------------------------------------
// Convert kernels: fp32 -> fp16.
// ---------------------------------------------------------------------------
__global__ void __launch_bounds__(256) cvth_kernel(
    const float* __restrict__ s, uint16_t* __restrict__ h, int n4)
{
    int i = blockIdx.x * 256 + threadIdx.x;
    if (i >= n4) return;
    float4 v = reinterpret_cast<const float4*>(s)[i];
    reinterpret_cast<uint2*>(h)[i] = make_uint2(packh(v.x, v.y), packh(v.z, v.w));
}
__global__ void __launch_bounds__(256) cvth3_kernel(
    const float* __restrict__ s0, const float* __restrict__ s1,
    const float* __restrict__ s2, uint16_t* __restrict__ h, int n4)
{
    int i = blockIdx.x * 256 + threadIdx.x;
    if (i >= n4) return;
    const float* s = (blockIdx.z == 0) ? s0 : (blockIdx.z == 1) ? s1 : s2;
    float4 v = reinterpret_cast<const float4*>(s)[i];
    reinterpret_cast<uint2*>(h + (size_t)blockIdx.z * DD * DD)[i] =
        make_uint2(packh(v.x, v.y), packh(v.z, v.w));
}

// ---------------------------------------------------------------------------
// Projection (merged Q/K/V): 1-pass fp16 HMMA. Y = Xh @ Wh^T + bias.
// 64(M)x128(N) tile, BK=32, 4 warps (1M x 4N), 128 threads, 3-stage pipe.
// ---------------------------------------------------------------------------
#define NSTAGE 3
#define NKT (DD / 32)
#define PROJ_STAGE_W 3072            // X 1024 + W 2048 words = 12 KB

__global__ void __launch_bounds__(128, 1) proj_mma(
    const float* __restrict__ bq, const float* __restrict__ bk,
    const float* __restrict__ bv)
{
    extern __shared__ uint32_t smw[];
    const uint32_t smb = smem_u32(smw);

    const int which = blockIdx.z;
    const float* bias = (which == 0) ? bq : (which == 1) ? bk : bv;

    const __half* Xh = (const __half*)g_Xh;
    const __half* Wh = (const __half*)(g_Wh + (size_t)which * DD * DD);

    const int tid = threadIdx.x;
    const int wid = tid >> 5, lane = tid & 31;
    const int g = lane >> 2, tig = lane & 3;
    const int wn = wid;
    const int m0 = blockIdx.y * 64, n0 = blockIdx.x * 128;

    const int lsub = lane >> 3, lr8 = lane & 7;
    const int a_radd = (lsub & 1) * 8 + lr8;
    const int a_cadd = lsub >> 1;
    const int b_radd = (lsub >> 1) * 8 + lr8;
    const int b_cadd = lsub & 1;

    auto load_stage = [&](int kt) {
        const int st = kt % NSTAGE;
        const int k0 = kt * 32;
        const uint32_t base = smb + (uint32_t)st * PROJ_STAGE_W * 4u;
        #pragma unroll
        for (int i = 0; i < 6; ++i) {
            const int idx = tid + 128 * i;          // 0..767
            uint32_t dst;
            const __half* src;
            if (idx < 256) {                        // X tile: 64 rows x 4 chunks
                const int row = idx >> 2, c = idx & 3;
                dst = base + 4u * (uint32_t)WOFF16(row, c * 4);
                src = Xh + (size_t)(m0 + row) * DD + k0 + c * 8;
            } else {                                // W tile: 128 rows x 4 chunks
                const int j = idx - 256;
                const int row = j >> 2, c = j & 3;
                dst = base + 4096u + 4u * (uint32_t)WOFF16(row, c * 4);
                src = Wh + (size_t)(n0 + row) * DD + k0 + c * 8;
            }
            cp_async16(dst, src);
        }
        CP_COMMIT();
    };

    float acc[4][4][4];
    #pragma unroll
    for (int i = 0; i < 4; ++i)
        #pragma unroll
        for (int j = 0; j < 4; ++j)
            #pragma unroll
            for (int r = 0; r < 4; ++r) acc[i][j][r] = 0.f;

    load_stage(0);
    load_stage(1);

    for (int kt = 0; kt < NKT; ++kt) {
        CP_WAIT(1);
        __syncthreads();
        if (kt + 2 < NKT) load_stage(kt + 2);
        else CP_COMMIT();

        const uint32_t base = smb + (uint32_t)(kt % NSTAGE) * PROJ_STAGE_W * 4u;
        const uint32_t Ah = base, Bh = base + 4096u;

        #pragma unroll
        for (int ks = 0; ks < 2; ++ks) {
            uint32_t bh[2][4];
            #pragma unroll
            for (int p = 0; p < 2; ++p) {
                const int rn = wn * 32 + p * 16 + b_radd;
                const uint32_t off = 4u * (uint32_t)WOFF16(rn, 4 * (2 * ks + b_cadd));
                ldsm4(bh[p], Bh + off);
            }
            #pragma unroll
            for (int mf = 0; mf < 4; ++mf) {
                const int rA = mf * 16 + a_radd;
                const uint32_t off = 4u * (uint32_t)WOFF16(rA, 4 * (2 * ks + a_cadd));
                uint32_t ah[4];
                ldsm4(ah, Ah + off);
                #pragma unroll
                for (int nf = 0; nf < 4; ++nf)
                    mma_f16(acc[mf][nf], ah, &bh[nf >> 1][(nf & 1) * 2]);
            }
        }
    }

    // ---- epilogue ----
    // Q pre-scaled by 0.125*log2(e) so QK^T emits log2-domain scores.
    const float qscale = (which == 0) ? 0.18033688011116027f : 1.0f;

    #pragma unroll
    for (int mf = 0; mf < 4; ++mf) {
        #pragma unroll
        for (int nf = 0; nf < 4; ++nf) {
            const int col = n0 + wn * 32 + nf * 8 + 2 * tig;
            const int h = col >> 6, dh = col & 63;
            const float2 bb = *reinterpret_cast<const float2*>(bias + col);
            #pragma unroll
            for (int half = 0; half < 2; ++half) {
                const int r = m0 + mf * 16 + g + 8 * half;
                const int b_ = r >> 11;
                const int sq = r & (SS - 1);
                const int bh_ = b_ * HH + h;
                const float y0 = (acc[mf][nf][2 * half + 0] + bb.x) * qscale;
                const float y1 = (acc[mf][nf][2 * half + 1] + bb.y) * qscale;
                const uint32_t h2 = packh(y0, y1);
                if (which == 0) {
                    *reinterpret_cast<uint32_t*>(
                        g_Qh + ((size_t)bh_ * SS + sq) * DHH + dh) = h2;
                } else if (which == 1) {
                    *reinterpret_cast<uint32_t*>(
                        g_Kh + ((size_t)bh_ * SS + sq) * DHH + dh) = h2;
                } else {
                    const size_t i0 = ((size_t)bh_ * DHH + dh) * SS + sq;
                    const size_t i1 = ((size_t)bh_ * DHH + dh + 1) * SS + sq;
                    g_Vth[i0] = (uint16_t)(h2 & 0xffff);
                    g_Vth[i1] = (uint16_t)(h2 >> 16);
                }
            }
        }
    }
}

// ---------------------------------------------------------------------------
// Flash attention, static-max (R10 structure): phase order QK -> exp -> PV,
// 8 independent accumulators per phase. Packed-half exp: packh(S) then
// ex2.f16x2 — halves MUFU ops; row sums add the exact fp16 P used by PV.
// 64 q-rows per CTA (4 warps), 64-key blocks, double-buffered.
// ---------------------------------------------------------------------------
#define ATTN_STAGE_W 4096            // 2 tiles (K, Vt) x 2048 words = 16 KB

__global__ void __launch_bounds__(128, 1) attn_mma(float* __restrict__ out)
{
    extern __shared__ uint32_t smw[];
    const uint32_t smb = smem_u32(smw);

    const int tid = threadIdx.x;
    const int wid = tid >> 5, lane = tid & 31;
    const int g = lane >> 2, tig = lane & 3;
    const int bx = (int)gridDim.x - 1 - (int)blockIdx.x;  // heavy tiles first
    const int bh = blockIdx.y;
    const int q0 = bx * 64;

    const int lsub = lane >> 3, lr8 = lane & 7;
    const int b_radd = (lsub >> 1) * 8 + lr8;
    const int b_cadd = lsub & 1;

    const __half* Qg  = (const __half*)g_Qh  + (size_t)bh * SS * DHH;
    const __half* Kg  = (const __half*)g_Kh  + (size_t)bh * SS * DHH;
    const __half* Vtg = (const __half*)g_Vth + (size_t)bh * DHH * SS;

    const int qrA = q0 + wid * 16 + g;

    // Q fragments (single fp16, pre-scaled 0.125*log2e)
    uint32_t qh[4][4];
    #pragma unroll
    for (int ks = 0; ks < 4; ++ks) {
        const int w0 = 8 * ks + tig, w1 = w0 + 4;
        const uint32_t* ra = reinterpret_cast<const uint32_t*>(Qg + (size_t)qrA * DHH);
        const uint32_t* rb = reinterpret_cast<const uint32_t*>(Qg + (size_t)(qrA + 8) * DHH);
        qh[ks][0] = ra[w0]; qh[ks][1] = rb[w0]; qh[ks][2] = ra[w1]; qh[ks][3] = rb[w1];
    }

    auto load_stage = [&](int kb) {
        const int k0 = kb * 64;
        const uint32_t base = smb + (uint32_t)(kb & 1) * ATTN_STAGE_W * 4u;
        #pragma unroll
        for (int i = 0; i < 8; ++i) {
            const int idx = tid + 128 * i;          // 0..1023
            const int tile = idx >> 9;
            const int rem = idx & 511;
            const int row = rem >> 3, c = rem & 7;
            const uint32_t dst = base + (uint32_t)tile * 8192u + 4u * (uint32_t)WOFF32(row, c * 4);
            const __half* src = (tile == 0)
                ? Kg  + (size_t)(k0 + row) * DHH + c * 8
                : Vtg + (size_t)row * SS + k0 + c * 8;
            cp_async16(dst, src);
        }
        CP_COMMIT();
    };

    float O[8][4];
    #pragma unroll
    for (int d = 0; d < 8; ++d)
        #pragma unroll
        for (int r = 0; r < 4; ++r) O[d][r] = 0.f;
    float rsA = 0.f, rsB = 0.f;      // per-thread partial row sums (fp32)

    const int nkb = bx + 1;
    load_stage(0);

    for (int kb = 0; kb < nkb; ++kb) {
        CP_WAIT(0);
        __syncthreads();
        if (kb + 1 < nkb) load_stage(kb + 1);

        const uint32_t base = smb + (uint32_t)(kb & 1) * ATTN_STAGE_W * 4u;
        const uint32_t KS = base, VS = base + 8192u;

        // ---- S = Q K^T (log2-domain scores) ----
        float S[8][4];
        #pragma unroll
        for (int nf = 0; nf < 8; ++nf)
            #pragma unroll
            for (int r = 0; r < 4; ++r) S[nf][r] = 0.f;

        #pragma unroll
        for (int ks = 0; ks < 4; ++ks) {
            #pragma unroll
            for (int p = 0; p < 4; ++p) {
                const int rn = p * 16 + b_radd;
                const uint32_t off = 4u * (uint32_t)WOFF32(rn, 4 * (2 * ks + b_cadd));
                uint32_t k4[4];
                ldsm4(k4, KS + off);
                mma_f16(S[2 * p],     qh[ks], k4);
                mma_f16(S[2 * p + 1], qh[ks], k4 + 2);
            }
        }

        // ---- causal mask (diagonal block only) ----
        if (kb == bx) {
            #pragma unroll
            for (int nf = 0; nf < 8; ++nf) {
                const int key = kb * 64 + nf * 8 + 2 * tig;
                if (key     > qrA)     S[nf][0] = -1e30f;
                if (key + 1 > qrA)     S[nf][1] = -1e30f;
                if (key     > qrA + 8) S[nf][2] = -1e30f;
                if (key + 1 > qrA + 8) S[nf][3] = -1e30f;
            }
        }

        // ---- P = exp2(S) via packed-half ex2; row sums from the same fp16 P ----
        uint32_t ph[4][4];
        #pragma unroll
        for (int k2 = 0; k2 < 4; ++k2) {
            ph[k2][0] = h2ex2(packh(S[2 * k2][0],     S[2 * k2][1]));      // row A
            ph[k2][1] = h2ex2(packh(S[2 * k2][2],     S[2 * k2][3]));      // row B
            ph[k2][2] = h2ex2(packh(S[2 * k2 + 1][0], S[2 * k2 + 1][1]));  // row A
            ph[k2][3] = h2ex2(packh(S[2 * k2 + 1][2], S[2 * k2 + 1][3]));  // row B
            const __half2 sA = __hadd2(*reinterpret_cast<const __half2*>(&ph[k2][0]),
                                       *reinterpret_cast<const __half2*>(&ph[k2][2]));
            const __half2 sB = __hadd2(*reinterpret_cast<const __half2*>(&ph[k2][1]),
                                       *reinterpret_cast<const __half2*>(&ph[k2][3]));
            const float2 fA = __half22float2(sA);
            const float2 fB = __half22float2(sB);
            rsA += fA.x + fA.y;
            rsB += fB.x + fB.y;
        }

        // ---- O += P V (1-pass fp16, no rescale) ----
        #pragma unroll
        for (int ks = 0; ks < 4; ++ks) {
            #pragma unroll
            for (int p = 0; p < 4; ++p) {
                const int rv = p * 16 + b_radd;
                const uint32_t off = 4u * (uint32_t)WOFF32(rv, 4 * (2 * ks + b_cadd));
                uint32_t v4[4];
                ldsm4(v4, VS + off);
                mma_f16(O[2 * p],     ph[ks], v4);
                mma_f16(O[2 * p + 1], ph[ks], v4 + 2);
            }
        }
    }

    // ---- final row-sum reduce (once) + normalize + store ----
    float lA = rsA, lB = rsB;
    lA += __shfl_xor_sync(0xffffffffu, lA, 1);
    lA += __shfl_xor_sync(0xffffffffu, lA, 2);
    lB += __shfl_xor_sync(0xffffffffu, lB, 1);
    lB += __shfl_xor_sync(0xffffffffu, lB, 2);

    const int b_ = bh >> 4, h = bh & 15;
    const float iA = 1.f / lA, iB = 1.f / lB;
    #pragma unroll
    for (int df = 0; df < 8; ++df) {
        const int col = h * DHH + df * 8 + 2 * tig;
        float2 va = { O[df][0] * iA, O[df][1] * iA };
        float2 vb = { O[df][2] * iB, O[df][3] * iB };
        *reinterpret_cast<float2*>(out + ((size_t)(b_ * SS + qrA)) * DD + col) = va;
        *reinterpret_cast<float2*>(out + ((size_t)(b_ * SS + qrA + 8)) * DD + col) = vb;
    }
}

// ---------------------------------------------------------------------------
// Launch
// ---------------------------------------------------------------------------
extern "C" void kernel_launch(void* const* d_in, const int* in_sizes, int n_in,
                              void* d_out, int out_size)
{
    const float* x  = (const float*)d_in[0];
    const float* Wq = (const float*)d_in[2];
    const float* bq = (const float*)d_in[3];
    const float* Wk = (const float*)d_in[4];
    const float* bk = (const float*)d_in[5];
    const float* Wv = (const float*)d_in[6];
    const float* bv = (const float*)d_in[7];
    float* out = (float*)d_out;

    void *pXh, *pWh;
    cudaGetSymbolAddress(&pXh, g_Xh);
    cudaGetSymbolAddress(&pWh, g_Wh);

    const int nX4 = BB * SS * DD / 4;
    const int nW4 = DD * DD / 4;
    cvth_kernel<<<(nX4 + 255) / 256, 256>>>(x, (uint16_t*)pXh, nX4);
    cvth3_kernel<<<dim3((nW4 + 255) / 256, 1, 3), 256>>>(Wq, Wk, Wv, (uint16_t*)pWh, nW4);

    const int PROJ_SMEM = NSTAGE * PROJ_STAGE_W * 4;   // 36 KB
    cudaFuncSetAttribute(proj_mma, cudaFuncAttributeMaxDynamicSharedMemorySize, PROJ_SMEM);
    const int ATTN_SMEM = 2 * ATTN_STAGE_W * 4;        // 32 KB
    cudaFuncSetAttribute(attn_mma, cudaFuncAttributeMaxDynamicSharedMemorySize, ATTN_SMEM);

    dim3 gp(DD / 128, (BB * SS) / 64, 3);              // (8, 128, 3)
    proj_mma<<<gp, 128, PROJ_SMEM>>>(bq, bk, bv);

    attn_mma<<<dim3(SS / 64, BB * HH), 128, ATTN_SMEM>>>(out);
}

// round 14
// speedup vs baseline: 1.0602x; 1.0558x over previous
#include <cuda_runtime.h>
#include <cuda_fp16.h>
#include <cstdint>
#include <cstddef>

#define BB 4
#define SS 2048
#define DD 1024
#define HH 16
#define DHH 64

// ---------------------------------------------------------------------------
// Scratch: everything single fp16.
// X: [BS, D]. W: [3][D, D]. Q (pre-scaled 0.125*log2e) / K: [BH,S,DH].
// Vt: [BH,DH,S].
// ---------------------------------------------------------------------------
__device__ uint16_t g_Xh[BB * SS * DD];
__device__ uint16_t g_Wh[3 * DD * DD];
__device__ uint16_t g_Qh[BB * HH * SS * DHH];
__device__ uint16_t g_Kh[BB * HH * SS * DHH];
__device__ uint16_t g_Vth[BB * HH * SS * DHH];

// ---------------------------------------------------------------------------
// Helpers
// ---------------------------------------------------------------------------
__device__ __forceinline__ uint32_t smem_u32(const void* p) {
    uint32_t a;
    asm("{ .reg .u64 t; cvta.to.shared.u64 t, %1; cvt.u32.u64 %0, t; }"
        : "=r"(a) : "l"(p));
    return a;
}
__device__ __forceinline__ void cp_async16(uint32_t dst, const void* src) {
    asm volatile("cp.async.cg.shared.global [%0], [%1], 16;"
                 :: "r"(dst), "l"(src) : "memory");
}
#define CP_COMMIT() asm volatile("cp.async.commit_group;" ::: "memory")
#define CP_WAIT(n)  asm volatile("cp.async.wait_group %0;" :: "n"(n) : "memory")

__device__ __forceinline__ void ldsm4(uint32_t* r, uint32_t addr) {
    asm volatile("ldmatrix.sync.aligned.m8n8.x4.shared.b16 {%0,%1,%2,%3}, [%4];"
                 : "=r"(r[0]), "=r"(r[1]), "=r"(r[2]), "=r"(r[3]) : "r"(addr));
}

__device__ __forceinline__ uint32_t packh(float x, float y) {
    uint32_t r;
    asm("cvt.rn.f16x2.f32 %0, %1, %2;" : "=r"(r) : "f"(y), "f"(x));
    return r;
}
__device__ __forceinline__ float ex2(float x) {
    float r;
    asm("ex2.approx.ftz.f32 %0, %1;" : "=f"(r) : "f"(x));
    return r;
}

__device__ __forceinline__ void mma_f16(float* d, const uint32_t* a, const uint32_t* b) {
    asm volatile(
        "mma.sync.aligned.m16n8k16.row.col.f32.f16.f16.f32 "
        "{%0,%1,%2,%3}, {%4,%5,%6,%7}, {%8,%9}, {%0,%1,%2,%3};"
        : "+f"(d[0]), "+f"(d[1]), "+f"(d[2]), "+f"(d[3])
        : "r"(a[0]), "r"(a[1]), "r"(a[2]), "r"(a[3]), "r"(b[0]), "r"(b[1]));
}

// Swizzled word offset, 32-word (64 fp16) rows.
#define WOFF32(r, w) ((r) * 32 + ((w) ^ (((r) & 7) << 2)))

// ---------------------------------------------------------------------------
// Convert kernels: fp32 -> fp16.
// ---------------------------------------------------------------------------
__global__ void __launch_bounds__(256) cvth_kernel(
    const float* __restrict__ s, uint16_t* __restrict__ h, int n4)
{
    int i = blockIdx.x * 256 + threadIdx.x;
    if (i >= n4) return;
    float4 v = reinterpret_cast<const float4*>(s)[i];
    reinterpret_cast<uint2*>(h)[i] = make_uint2(packh(v.x, v.y), packh(v.z, v.w));
}
__global__ void __launch_bounds__(256) cvth3_kernel(
    const float* __restrict__ s0, const float* __restrict__ s1,
    const float* __restrict__ s2, uint16_t* __restrict__ h, int n4)
{
    int i = blockIdx.x * 256 + threadIdx.x;
    if (i >= n4) return;
    const float* s = (blockIdx.z == 0) ? s0 : (blockIdx.z == 1) ? s1 : s2;
    float4 v = reinterpret_cast<const float4*>(s)[i];
    reinterpret_cast<uint2*>(h + (size_t)blockIdx.z * DD * DD)[i] =
        make_uint2(packh(v.x, v.y), packh(v.z, v.w));
}

// ---------------------------------------------------------------------------
// Projection (merged Q/K/V): 1-pass fp16 HMMA. Y = Xh @ Wh^T + bias.
// 64(M)x128(N) tile, BK=64 (one barrier per 64 mma), 4 warps, 3-stage pipe.
// Stage: X 64x64 (8KB, WOFF32) + W 128x64 (16KB, WOFF32) = 24KB.
// ---------------------------------------------------------------------------
#define NSTAGE 3
#define NKT (DD / 64)                // 16 iterations
#define PROJ_STAGE_W 6144            // 24 KB in words

__global__ void __launch_bounds__(128, 1) proj_mma(
    const float* __restrict__ bq, const float* __restrict__ bk,
    const float* __restrict__ bv)
{
    extern __shared__ uint32_t smw[];
    const uint32_t smb = smem_u32(smw);

    const int which = blockIdx.z;
    const float* bias = (which == 0) ? bq : (which == 1) ? bk : bv;

    const __half* Xh = (const __half*)g_Xh;
    const __half* Wh = (const __half*)(g_Wh + (size_t)which * DD * DD);

    const int tid = threadIdx.x;
    const int wid = tid >> 5, lane = tid & 31;
    const int g = lane >> 2, tig = lane & 3;
    const int wn = wid;
    const int m0 = blockIdx.y * 64, n0 = blockIdx.x * 128;

    const int lsub = lane >> 3, lr8 = lane & 7;
    const int a_radd = (lsub & 1) * 8 + lr8;
    const int a_cadd = lsub >> 1;
    const int b_radd = (lsub >> 1) * 8 + lr8;
    const int b_cadd = lsub & 1;

    auto load_stage = [&](int kt) {
        const int st = kt % NSTAGE;
        const int k0 = kt * 64;
        const uint32_t base = smb + (uint32_t)st * PROJ_STAGE_W * 4u;
        #pragma unroll
        for (int i = 0; i < 12; ++i) {
            const int idx = tid + 128 * i;          // 0..1535
            uint32_t dst;
            const __half* src;
            if (idx < 512) {                        // X tile: 64 rows x 8 chunks
                const int row = idx >> 3, c = idx & 7;
                dst = base + 4u * (uint32_t)WOFF32(row, c * 4);
                src = Xh + (size_t)(m0 + row) * DD + k0 + c * 8;
            } else {                                // W tile: 128 rows x 8 chunks
                const int j = idx - 512;
                const int row = j >> 3, c = j & 7;
                dst = base + 8192u + 4u * (uint32_t)WOFF32(row, c * 4);
                src = Wh + (size_t)(n0 + row) * DD + k0 + c * 8;
            }
            cp_async16(dst, src);
        }
        CP_COMMIT();
    };

    float acc[4][4][4];
    #pragma unroll
    for (int i = 0; i < 4; ++i)
        #pragma unroll
        for (int j = 0; j < 4; ++j)
            #pragma unroll
            for (int r = 0; r < 4; ++r) acc[i][j][r] = 0.f;

    load_stage(0);
    load_stage(1);

    for (int kt = 0; kt < NKT; ++kt) {
        CP_WAIT(1);
        __syncthreads();
        if (kt + 2 < NKT) load_stage(kt + 2);
        else CP_COMMIT();

        const uint32_t base = smb + (uint32_t)(kt % NSTAGE) * PROJ_STAGE_W * 4u;
        const uint32_t Ah = base, Bh = base + 8192u;

        #pragma unroll
        for (int ks = 0; ks < 4; ++ks) {
            uint32_t bh[2][4];
            #pragma unroll
            for (int p = 0; p < 2; ++p) {
                const int rn = wn * 32 + p * 16 + b_radd;
                const uint32_t off = 4u * (uint32_t)WOFF32(rn, 4 * (2 * ks + b_cadd));
                ldsm4(bh[p], Bh + off);
            }
            #pragma unroll
            for (int mf = 0; mf < 4; ++mf) {
                const int rA = mf * 16 + a_radd;
                const uint32_t off = 4u * (uint32_t)WOFF32(rA, 4 * (2 * ks + a_cadd));
                uint32_t ah[4];
                ldsm4(ah, Ah + off);
                #pragma unroll
                for (int nf = 0; nf < 4; ++nf)
                    mma_f16(acc[mf][nf], ah, &bh[nf >> 1][(nf & 1) * 2]);
            }
        }
    }

    // ---- epilogue ----
    // Q pre-scaled by 0.125*log2(e) so QK^T emits log2-domain scores.
    const float qscale = (which == 0) ? 0.18033688011116027f : 1.0f;

    #pragma unroll
    for (int mf = 0; mf < 4; ++mf) {
        #pragma unroll
        for (int nf = 0; nf < 4; ++nf) {
            const int col = n0 + wn * 32 + nf * 8 + 2 * tig;
            const int h = col >> 6, dh = col & 63;
            const float2 bb = *reinterpret_cast<const float2*>(bias + col);
            #pragma unroll
            for (int half = 0; half < 2; ++half) {
                const int r = m0 + mf * 16 + g + 8 * half;
                const int b_ = r >> 11;
                const int sq = r & (SS - 1);
                const int bh_ = b_ * HH + h;
                const float y0 = (acc[mf][nf][2 * half + 0] + bb.x) * qscale;
                const float y1 = (acc[mf][nf][2 * half + 1] + bb.y) * qscale;
                const uint32_t h2 = packh(y0, y1);
                if (which == 0) {
                    *reinterpret_cast<uint32_t*>(
                        g_Qh + ((size_t)bh_ * SS + sq) * DHH + dh) = h2;
                } else if (which == 1) {
                    *reinterpret_cast<uint32_t*>(
                        g_Kh + ((size_t)bh_ * SS + sq) * DHH + dh) = h2;
                } else {
                    const size_t i0 = ((size_t)bh_ * DHH + dh) * SS + sq;
                    const size_t i1 = ((size_t)bh_ * DHH + dh + 1) * SS + sq;
                    g_Vth[i0] = (uint16_t)(h2 & 0xffff);
                    g_Vth[i1] = (uint16_t)(h2 >> 16);
                }
            }
        }
    }
}

// ---------------------------------------------------------------------------
// Flash attention, static-max (R10 math exactly): 128-key stages computed as
// two 64-key passes per barrier — half the sync density. 64 q-rows per CTA
// (4 warps), double-buffered 32KB stages (4 x 8KB WOFF32 sub-tiles:
// K0,K1,V0,V1). Over-read of a trailing odd sub-block stays within SS.
// ---------------------------------------------------------------------------
#define ATTN_STAGE_W 8192            // 32 KB in words

__global__ void __launch_bounds__(128, 1) attn_mma(float* __restrict__ out)
{
    extern __shared__ uint32_t smw[];
    const uint32_t smb = smem_u32(smw);

    const int tid = threadIdx.x;
    const int wid = tid >> 5, lane = tid & 31;
    const int g = lane >> 2, tig = lane & 3;
    const int bx = (int)gridDim.x - 1 - (int)blockIdx.x;  // heavy tiles first
    const int bh = blockIdx.y;
    const int q0 = bx * 64;

    const int lsub = lane >> 3, lr8 = lane & 7;
    const int b_radd = (lsub >> 1) * 8 + lr8;
    const int b_cadd = lsub & 1;

    const __half* Qg  = (const __half*)g_Qh  + (size_t)bh * SS * DHH;
    const __half* Kg  = (const __half*)g_Kh  + (size_t)bh * SS * DHH;
    const __half* Vtg = (const __half*)g_Vth + (size_t)bh * DHH * SS;

    const int qrA = q0 + wid * 16 + g;

    // Q fragments (single fp16, pre-scaled 0.125*log2e)
    uint32_t qh[4][4];
    #pragma unroll
    for (int ks = 0; ks < 4; ++ks) {
        const int w0 = 8 * ks + tig, w1 = w0 + 4;
        const uint32_t* ra = reinterpret_cast<const uint32_t*>(Qg + (size_t)qrA * DHH);
        const uint32_t* rb = reinterpret_cast<const uint32_t*>(Qg + (size_t)(qrA + 8) * DHH);
        qh[ks][0] = ra[w0]; qh[ks][1] = rb[w0]; qh[ks][2] = ra[w1]; qh[ks][3] = rb[w1];
    }

    // Stage layout: [K sub0 | K sub1 | V sub0 | V sub1], 8KB each.
    auto load_stage = [&](int st) {
        const int k0 = st * 128;
        const uint32_t base = smb + (uint32_t)(st & 1) * ATTN_STAGE_W * 4u;
        #pragma unroll
        for (int i = 0; i < 16; ++i) {
            const int idx = tid + 128 * i;          // 0..2047
            const int tile = idx >> 9;              // 0..3
            const int rem = idx & 511;
            const int row = rem >> 3, c = rem & 7;
            const uint32_t dst = base + (uint32_t)tile * 8192u
                               + 4u * (uint32_t)WOFF32(row, c * 4);
            const __half* src;
            if (tile < 2)  src = Kg  + (size_t)(k0 + (tile & 1) * 64 + row) * DHH + c * 8;
            else           src = Vtg + (size_t)row * SS + k0 + (tile & 1) * 64 + c * 8;
            cp_async16(dst, src);
        }
        CP_COMMIT();
    };

    float O[8][4];
    #pragma unroll
    for (int d = 0; d < 8; ++d)
        #pragma unroll
        for (int r = 0; r < 4; ++r) O[d][r] = 0.f;
    float rsA = 0.f, rsB = 0.f;      // per-thread partial row sums

    const int nkb = bx + 1;
    const int nst = (nkb + 1) >> 1;
    load_stage(0);

    for (int st = 0; st < nst; ++st) {
        CP_WAIT(0);
        __syncthreads();
        if (st + 1 < nst) load_stage(st + 1);

        const uint32_t base = smb + (uint32_t)(st & 1) * ATTN_STAGE_W * 4u;

        #pragma unroll
        for (int sub = 0; sub < 2; ++sub) {
            const int kb = 2 * st + sub;
            if (kb >= nkb) break;
            const uint32_t KS = base + (uint32_t)sub * 8192u;
            const uint32_t VS = base + 16384u + (uint32_t)sub * 8192u;

            // ---- S = Q K^T (log2-domain scores) ----
            float S[8][4];
            #pragma unroll
            for (int nf = 0; nf < 8; ++nf)
                #pragma unroll
                for (int r = 0; r < 4; ++r) S[nf][r] = 0.f;

            #pragma unroll
            for (int ks = 0; ks < 4; ++ks) {
                #pragma unroll
                for (int p = 0; p < 4; ++p) {
                    const int rn = p * 16 + b_radd;
                    const uint32_t off = 4u * (uint32_t)WOFF32(rn, 4 * (2 * ks + b_cadd));
                    uint32_t k4[4];
                    ldsm4(k4, KS + off);
                    mma_f16(S[2 * p],     qh[ks], k4);
                    mma_f16(S[2 * p + 1], qh[ks], k4 + 2);
                }
            }

            // ---- causal mask (diagonal block only) ----
            if (kb == bx) {
                #pragma unroll
                for (int nf = 0; nf < 8; ++nf) {
                    const int key = kb * 64 + nf * 8 + 2 * tig;
                    if (key     > qrA)     S[nf][0] = -1e30f;
                    if (key + 1 > qrA)     S[nf][1] = -1e30f;
                    if (key     > qrA + 8) S[nf][2] = -1e30f;
                    if (key + 1 > qrA + 8) S[nf][3] = -1e30f;
                }
            }

            // ---- P = exp2(S), accumulate row sums ----
            #pragma unroll
            for (int nf = 0; nf < 8; ++nf) {
                S[nf][0] = ex2(S[nf][0]); rsA += S[nf][0];
                S[nf][1] = ex2(S[nf][1]); rsA += S[nf][1];
                S[nf][2] = ex2(S[nf][2]); rsB += S[nf][2];
                S[nf][3] = ex2(S[nf][3]); rsB += S[nf][3];
            }

            // ---- P: repack into single fp16 A fragments ----
            uint32_t ph[4][4];
            #pragma unroll
            for (int k2 = 0; k2 < 4; ++k2) {
                ph[k2][0] = packh(S[2 * k2][0],     S[2 * k2][1]);
                ph[k2][1] = packh(S[2 * k2][2],     S[2 * k2][3]);
                ph[k2][2] = packh(S[2 * k2 + 1][0], S[2 * k2 + 1][1]);
                ph[k2][3] = packh(S[2 * k2 + 1][2], S[2 * k2 + 1][3]);
            }

            // ---- O += P V (1-pass fp16, no rescale) ----
            #pragma unroll
            for (int ks = 0; ks < 4; ++ks) {
                #pragma unroll
                for (int p = 0; p < 4; ++p) {
                    const int rv = p * 16 + b_radd;
                    const uint32_t off = 4u * (uint32_t)WOFF32(rv, 4 * (2 * ks + b_cadd));
                    uint32_t v4[4];
                    ldsm4(v4, VS + off);
                    mma_f16(O[2 * p],     ph[ks], v4);
                    mma_f16(O[2 * p + 1], ph[ks], v4 + 2);
                }
            }
        }
    }

    // ---- final row-sum reduce (once) + normalize + store ----
    float lA = rsA, lB = rsB;
    lA += __shfl_xor_sync(0xffffffffu, lA, 1);
    lA += __shfl_xor_sync(0xffffffffu, lA, 2);
    lB += __shfl_xor_sync(0xffffffffu, lB, 1);
    lB += __shfl_xor_sync(0xffffffffu, lB, 2);

    const int b_ = bh >> 4, h = bh & 15;
    const float iA = 1.f / lA, iB = 1.f / lB;
    #pragma unroll
    for (int df = 0; df < 8; ++df) {
        const int col = h * DHH + df * 8 + 2 * tig;
        float2 va = { O[df][0] * iA, O[df][1] * iA };
        float2 vb = { O[df][2] * iB, O[df][3] * iB };
        *reinterpret_cast<float2*>(out + ((size_t)(b_ * SS + qrA)) * DD + col) = va;
        *reinterpret_cast<float2*>(out + ((size_t)(b_ * SS + qrA + 8)) * DD + col) = vb;
    }
}

// ---------------------------------------------------------------------------
// Launch
// ---------------------------------------------------------------------------
extern "C" void kernel_launch(void* const* d_in, const int* in_sizes, int n_in,
                              void* d_out, int out_size)
{
    const float* x  = (const float*)d_in[0];
    const float* Wq = (const float*)d_in[2];
    const float* bq = (const float*)d_in[3];
    const float* Wk = (const float*)d_in[4];
    const float* bk = (const float*)d_in[5];
    const float* Wv = (const float*)d_in[6];
    const float* bv = (const float*)d_in[7];
    float* out = (float*)d_out;

    void *pXh, *pWh;
    cudaGetSymbolAddress(&pXh, g_Xh);
    cudaGetSymbolAddress(&pWh, g_Wh);

    const int nX4 = BB * SS * DD / 4;
    const int nW4 = DD * DD / 4;
    cvth_kernel<<<(nX4 + 255) / 256, 256>>>(x, (uint16_t*)pXh, nX4);
    cvth3_kernel<<<dim3((nW4 + 255) / 256, 1, 3), 256>>>(Wq, Wk, Wv, (uint16_t*)pWh, nW4);

    const int PROJ_SMEM = NSTAGE * PROJ_STAGE_W * 4;   // 72 KB
    cudaFuncSetAttribute(proj_mma, cudaFuncAttributeMaxDynamicSharedMemorySize, PROJ_SMEM);
    const int ATTN_SMEM = 2 * ATTN_STAGE_W * 4;        // 64 KB
    cudaFuncSetAttribute(attn_mma, cudaFuncAttributeMaxDynamicSharedMemorySize, ATTN_SMEM);

    dim3 gp(DD / 128, (BB * SS) / 64, 3);              // (8, 128, 3)
    proj_mma<<<gp, 128, PROJ_SMEM>>>(bq, bk, bv);

    attn_mma<<<dim3(SS / 64, BB * HH), 128, ATTN_SMEM>>>(out);
}